// round 14
// baseline (speedup 1.0000x reference)
#include <cuda_runtime.h>
#include <cuda_fp16.h>
#include <math.h>
#include <stdint.h>

// Problem constants
#define BB 128
#define NN 1024
#define UU 128
#define NM 3
#define SBLK 132           // per-step block: 128 hvec + 1 inp + 3 pad
#define KPAD 416           // 3*132 = 396 -> 416 (26 x 16)
#define NCH (KPAD / 16)    // 26 k-chunks
#define MROWS 131072
#define MAX_NNZ 64

// g_Xh row layout (stride KPAD, fp16):
//   [0..127] x0 hvec  [128] x0 inp [129..131] pad
//   [132..259] x1     [260] x1 inp [261..263] pad
//   [264..391] x2     [392] x2 inp [393..415] pad

// ---------------- scratch -----------------------------------------------------
__device__ __half g_h16[(size_t)MROWS * UU];    // fp16 copy of h input
__device__ __half g_Xh[(size_t)MROWS * KPAD];   // fp16 Xcat (A operand)
__device__ __half g_rh[(size_t)MROWS * UU];     // r*h (fp16)
__device__ float  g_u [(size_t)MROWS * UU];
__device__ __half g_Wgt[256 * KPAD];            // gate W^T [N][K] fp16
__device__ __half g_Wct[128 * KPAD];            // cand W^T [N][K] fp16
__device__ int    g_csr_cnt[NN];
__device__ int    g_csr_col[NN * MAX_NNZ];
__device__ float  g_csr_val[NN * MAX_NNZ];

// ---------------- helpers -----------------------------------------------------
__device__ __forceinline__ unsigned smem_u32(const void* p) {
    return (unsigned)__cvta_generic_to_shared(p);
}
__device__ __forceinline__ void cp16(unsigned dst, const void* src) {
    asm volatile("cp.async.cg.shared.global [%0], [%1], 16;" :: "r"(dst), "l"(src));
}
__device__ __forceinline__ void cp_commit() { asm volatile("cp.async.commit_group;"); }
__device__ __forceinline__ void cp_wait0()  { asm volatile("cp.async.wait_group 0;"); }

__device__ __forceinline__ void ldsm_x4(uint32_t* r, uint32_t a) {
    asm volatile("ldmatrix.sync.aligned.m8n8.x4.shared.b16 {%0,%1,%2,%3}, [%4];"
                 : "=r"(r[0]), "=r"(r[1]), "=r"(r[2]), "=r"(r[3]) : "r"(a));
}
__device__ __forceinline__ void ldsm_x2(uint32_t* r, uint32_t a) {
    asm volatile("ldmatrix.sync.aligned.m8n8.x2.shared.b16 {%0,%1}, [%2];"
                 : "=r"(r[0]), "=r"(r[1]) : "r"(a));
}
__device__ __forceinline__ void mma_f16(float* c, const uint32_t* a, const uint32_t* b) {
    asm volatile("mma.sync.aligned.m16n8k16.row.col.f32.f16.f16.f32 "
                 "{%0,%1,%2,%3}, {%4,%5,%6,%7}, {%8,%9}, {%0,%1,%2,%3};"
                 : "+f"(c[0]), "+f"(c[1]), "+f"(c[2]), "+f"(c[3])
                 : "r"(a[0]), "r"(a[1]), "r"(a[2]), "r"(a[3]), "r"(b[0]), "r"(b[1]));
}

__device__ __forceinline__ void h_store4(__half* p, float4 v) {
    __half2 h01 = __floats2half2_rn(v.x, v.y);
    __half2 h23 = __floats2half2_rn(v.z, v.w);
    uint2 u; u.x = *(uint32_t*)&h01; u.y = *(uint32_t*)&h23;
    *(uint2*)p = u;
}
__device__ __forceinline__ void h_store1pad(__half* p, float v) {
    __half2 h = __floats2half2_rn(v, 0.f);
    uint2 u; u.x = *(uint32_t*)&h; u.y = 0u;
    *(uint2*)p = u;
}
__device__ __forceinline__ float4 h_load4(const __half* p) {
    uint2 u = *(const uint2*)p;
    __half2 p01 = *(__half2*)&u.x, p23 = *(__half2*)&u.y;
    float2 f01 = __half22float2(p01), f23 = __half22float2(p23);
    return make_float4(f01.x, f01.y, f23.x, f23.y);
}
__device__ __forceinline__ void fma4(float4& a, float s, float4 v) {
    a.x = fmaf(s, v.x, a.x); a.y = fmaf(s, v.y, a.y);
    a.z = fmaf(s, v.z, a.z); a.w = fmaf(s, v.w, a.w);
}

// 4-way unrolled fp16 sparse gather with 4 INDEPENDENT accumulators
// (breaks the serial FMA chain: depth 4 instead of 16 per unroll block).
__device__ __forceinline__ void gather_acc_h(
    const __half* __restrict__ base, size_t rowstride, int lane,
    const int* scol, const float* sval, int cnt,
    const float* sextra, float4& aout, float& a1out, bool lane0)
{
    float4 a0 = make_float4(0.f,0.f,0.f,0.f), a1v = a0, a2 = a0, a3 = a0;
    float e0 = 0.f, e1 = 0.f, e2 = 0.f, e3 = 0.f;
    int i = 0;
    for (; i + 4 <= cnt; i += 4) {
        int n0 = scol[i], n1 = scol[i+1], n2 = scol[i+2], n3 = scol[i+3];
        float s0 = sval[i], s1 = sval[i+1], s2 = sval[i+2], s3 = sval[i+3];
        float4 v0 = h_load4(base + (size_t)n0 * rowstride + lane * 4);
        float4 v1 = h_load4(base + (size_t)n1 * rowstride + lane * 4);
        float4 v2 = h_load4(base + (size_t)n2 * rowstride + lane * 4);
        float4 v3 = h_load4(base + (size_t)n3 * rowstride + lane * 4);
        fma4(a0, s0, v0);
        fma4(a1v, s1, v1);
        fma4(a2, s2, v2);
        fma4(a3, s3, v3);
        if (lane0) {
            e0 = fmaf(s0, sextra[i],   e0);
            e1 = fmaf(s1, sextra[i+1], e1);
            e2 = fmaf(s2, sextra[i+2], e2);
            e3 = fmaf(s3, sextra[i+3], e3);
        }
    }
    for (; i < cnt; i++) {
        float s = sval[i];
        float4 v = h_load4(base + (size_t)scol[i] * rowstride + lane * 4);
        fma4(a0, s, v);
        if (lane0) e0 = fmaf(s, sextra[i], e0);
    }
    a0.x += a1v.x; a0.y += a1v.y; a0.z += a1v.z; a0.w += a1v.w;
    a2.x += a3.x;  a2.y += a3.y;  a2.z += a3.z;  a2.w += a3.w;
    aout.x = a0.x + a2.x; aout.y = a0.y + a2.y;
    aout.z = a0.z + a2.z; aout.w = a0.w + a2.w;
    a1out = (e0 + e1) + (e2 + e3);
}

// ---------------- merged setup: h2half | csr_build | wtrans x2 ----------------
// grid layout (all blocks 256 thr):
//   [0, 16384)            h -> fp16
//   [16384, 16512)        CSR build (128 blocks)
//   [16512, 16512+KPAD)   wtrans gate
//   [16512+KPAD, +2*KPAD) wtrans cand
#define SETUP_H2H   16384
#define SETUP_CSR   (SETUP_H2H + 128)
#define SETUP_WG    (SETUP_CSR + KPAD)
#define SETUP_TOTAL (SETUP_WG + KPAD)

__global__ void __launch_bounds__(256) setup_all(
    const float* __restrict__ h, const float* __restrict__ S,
    const float* __restrict__ gw, const float* __restrict__ cw)
{
    int bx = blockIdx.x, tid = threadIdx.x;
    if (bx < SETUP_H2H) {
        size_t i = (size_t)bx * 256 + tid;
        float4 v = *(const float4*)(h + i * 4);
        h_store4(g_h16 + i * 4, v);
    } else if (bx < SETUP_CSR) {
        int w = ((bx - SETUP_H2H) * 256 + tid) >> 5;
        int lane = tid & 31;
        if (w >= NN) return;
        const float* row = S + (size_t)w * NN;
        int cnt = 0;
        for (int base = 0; base < NN; base += 32) {
            float v = row[base + lane];
            unsigned m = __ballot_sync(0xffffffffu, v != 0.f);
            if (v != 0.f) {
                int pos = cnt + __popc(m & ((1u << lane) - 1u));
                if (pos < MAX_NNZ) {
                    g_csr_col[w * MAX_NNZ + pos] = base + lane;
                    g_csr_val[w * MAX_NNZ + pos] = v;
                }
            }
            cnt += __popc(m);
        }
        if (lane == 0) g_csr_cnt[w] = cnt < MAX_NNZ ? cnt : MAX_NNZ;
    } else if (bx < SETUP_WG) {
        int k = bx - SETUP_CSR, j = tid;           // gate: 256 cols
        int s = k / SBLK, c = k - s * SBLK;
        float v = 0.f;
        if (s < NM && c < 129) {
            int corig = (c == 128) ? 0 : (c + 1);
            v = gw[(size_t)(corig * NM + s) * 256 + j];
        }
        g_Wgt[(size_t)j * KPAD + k] = __float2half_rn(v);
    } else {
        int k = bx - SETUP_WG, j = tid;            // cand: 128 cols
        if (j >= 128) return;
        int s = k / SBLK, c = k - s * SBLK;
        float v = 0.f;
        if (s < NM && c < 129) {
            int corig = (c == 128) ? 0 : (c + 1);
            v = cw[(size_t)(corig * NM + s) * 128 + j];
        }
        g_Wct[(size_t)j * KPAD + k] = __float2half_rn(v);
    }
}

// ---------------- diffusion pass 1: x0 copy + x1 (=S@x0), all fp16 ------------
template <int USE_RH>
__global__ void __launch_bounds__(128) spmm_pass1(const float* __restrict__ inp) {
    const __half* __restrict__ hvec = USE_RH ? (const __half*)g_rh : (const __half*)g_h16;
    int m = blockIdx.x;
    int g = threadIdx.x >> 5, lane = threadIdx.x & 31;
    int b = blockIdx.y * 4 + g;
    __shared__ int   scol[MAX_NNZ];
    __shared__ float sval[MAX_NNZ];
    __shared__ float sinp[4][MAX_NNZ];
    int cnt = g_csr_cnt[m];
    if (threadIdx.x < MAX_NNZ) {
        scol[threadIdx.x] = g_csr_col[m * MAX_NNZ + threadIdx.x];
        sval[threadIdx.x] = g_csr_val[m * MAX_NNZ + threadIdx.x];
    }
    __syncthreads();
    if (lane < cnt) sinp[g][lane] = inp[(size_t)b * NN + scol[lane]];
    if (cnt > 32 && lane + 32 < cnt) sinp[g][lane + 32] = inp[(size_t)b * NN + scol[lane + 32]];
    __syncwarp();

    size_t rowm = (size_t)b * NN + m;
    float4 a; float a1;
    gather_acc_h(hvec + (size_t)b * NN * UU, UU, lane, scol, sval, cnt,
                 sinp[g], a, a1, lane == 0);

    __half* Xh = g_Xh + rowm * KPAD;
    *(uint2*)(Xh + lane * 4) = *(const uint2*)(hvec + rowm * UU + lane * 4);
    h_store4(Xh + 132 + lane * 4, a);
    if (lane == 0) {
        h_store1pad(Xh + 128, inp[rowm]);   // x0 inp + pads 129..131
        h_store1pad(Xh + 260, a1);          // x1 inp + pads 261..263
    }
}

// ---------------- diffusion pass 2: x2 = 2*S@x1 - x0 (x1 from Xh cols 132+) ---
template <int USE_RH>
__global__ void __launch_bounds__(128) spmm_pass2(const float* __restrict__ inp) {
    const __half* __restrict__ hvec = USE_RH ? (const __half*)g_rh : (const __half*)g_h16;
    int m = blockIdx.x;
    int g = threadIdx.x >> 5, lane = threadIdx.x & 31;
    int b = blockIdx.y * 4 + g;
    __shared__ int   scol[MAX_NNZ];
    __shared__ float sval[MAX_NNZ];
    __shared__ float sx1i[4][MAX_NNZ];
    int cnt = g_csr_cnt[m];
    if (threadIdx.x < MAX_NNZ) {
        scol[threadIdx.x] = g_csr_col[m * MAX_NNZ + threadIdx.x];
        sval[threadIdx.x] = g_csr_val[m * MAX_NNZ + threadIdx.x];
    }
    __syncthreads();
    if (lane < cnt)
        sx1i[g][lane] = __half2float(g_Xh[((size_t)b * NN + scol[lane]) * KPAD + 260]);
    if (cnt > 32 && lane + 32 < cnt)
        sx1i[g][lane + 32] = __half2float(g_Xh[((size_t)b * NN + scol[lane + 32]) * KPAD + 260]);
    __syncwarp();

    size_t rowm = (size_t)b * NN + m;
    float4 a; float a1;
    gather_acc_h(g_Xh + (size_t)b * NN * KPAD + 132, KPAD, lane, scol, sval, cnt,
                 sx1i[g], a, a1, lane == 0);

    float4 x0 = h_load4(hvec + rowm * UU + lane * 4);
    float4 r;
    r.x = 2.f * a.x - x0.x;
    r.y = 2.f * a.y - x0.y;
    r.z = 2.f * a.z - x0.z;
    r.w = 2.f * a.w - x0.w;

    __half* Xh = g_Xh + rowm * KPAD;
    h_store4(Xh + 264 + lane * 4, r);                            // cols 264..391
    if (lane == 0) h_store1pad(Xh + 392, 2.f * a1 - inp[rowm]);  // 392..395
    if (lane < 5) {                                              // pads 396..415
        uint2 z; z.x = 0u; z.y = 0u;
        *(uint2*)(Xh + 396 + lane * 4) = z;
    }
}

// ---------------- fp16 tensor-core GEMM ---------------------------------------
// BM=128 BN=128 BK=16, 256 thr (8 warps 4Mx2N), warp tile 32x64, m16n8k16.
// MODE 0: gate (Wgt, N=256, grid.y=2): by0 -> g_rh(fp16) = sig*h ; by1 -> g_u = sig
// MODE 1: cand (Wct, N=128): newh = u*h+(1-u)*tanh ; fused proj -> out
template <int MODE>
__global__ void __launch_bounds__(256) gemm_kernel(
    const float* __restrict__ bias, const float* __restrict__ hvec,
    float* __restrict__ newh, const float* __restrict__ pw,
    const float* __restrict__ pb, float* __restrict__ out)
{
    __shared__ __align__(16) char smem_raw[2 * 2 * 128 * 24 * 2];   // 24576 B
    typedef __half (*SMv)[2][128 * 24];
    SMv SM = (SMv)smem_raw;
    float* srow = (float*)smem_raw;            // aliased; post-mainloop only

    const int tid = threadIdx.x;
    const int lane = tid & 31, wid = tid >> 5;
    const int wm = wid >> 1, wn = wid & 1;
    const size_t mbase = (size_t)blockIdx.x * 128;
    const int jb = (MODE == 0) ? blockIdx.y * 128 : 0;

    const __half* __restrict__ Wt = (MODE == 0) ? g_Wgt : g_Wct;

    const int lrow = tid >> 1, lhalf = tid & 1;
    const __half* srcA = g_Xh + (mbase + lrow) * KPAD + lhalf * 8;
    const __half* srcB = Wt + (size_t)(jb + lrow) * KPAD + lhalf * 8;
    const int dsti = lrow * 24 + lhalf * 8;

    float c[2][8][4];
#pragma unroll
    for (int mt = 0; mt < 2; mt++)
#pragma unroll
        for (int j = 0; j < 8; j++)
#pragma unroll
            for (int q = 0; q < 4; q++) c[mt][j][q] = 0.f;

    {
        cp16(smem_u32(&SM[0][0][dsti]), srcA);
        cp16(smem_u32(&SM[0][1][dsti]), srcB);
        cp_commit();
    }

    const int la = lane & 15;
    const int ka = (lane & 16) ? 8 : 0;
    const int arow = wm * 32 + la;
    const int nb = lane & 7;
    const int kb = (lane & 8) ? 8 : 0;

    for (int t = 0; t < NCH; t++) {
        int cur = t & 1, nxt = cur ^ 1;
        cp_wait0();
        __syncthreads();
        if (t + 1 < NCH) {
            int k0 = (t + 1) * 16;
            cp16(smem_u32(&SM[nxt][0][dsti]), srcA + k0);
            cp16(smem_u32(&SM[nxt][1][dsti]), srcB + k0);
            cp_commit();
        }

        uint32_t ah[2][4];
#pragma unroll
        for (int mt = 0; mt < 2; mt++)
            ldsm_x4(ah[mt], smem_u32(&SM[cur][0][(arow + mt * 16) * 24 + ka]));
#pragma unroll
        for (int j = 0; j < 8; j++) {
            uint32_t bh[2];
            int bi = (wn * 64 + j * 8 + nb) * 24 + kb;
            ldsm_x2(bh, smem_u32(&SM[cur][1][bi]));
#pragma unroll
            for (int mt = 0; mt < 2; mt++)
                mma_f16(c[mt][j], ah[mt], bh);
        }
    }

    // epilogue
    float part[2][2];
    if (MODE == 1) { part[0][0] = part[0][1] = part[1][0] = part[1][1] = 0.f; }

#pragma unroll
    for (int mt = 0; mt < 2; mt++) {
#pragma unroll
        for (int j = 0; j < 8; j++) {
            int row0 = (int)mbase + wm * 32 + mt * 16 + (lane >> 2);
            int col = wn * 64 + j * 8 + (lane & 3) * 2;
            int jg = jb + col;
            float b0 = bias[jg], b1 = bias[jg + 1];
#pragma unroll
            for (int h2 = 0; h2 < 2; h2++) {
                int row = row0 + h2 * 8;
                float v0 = c[mt][j][h2 * 2 + 0] + b0;
                float v1 = c[mt][j][h2 * 2 + 1] + b1;
                size_t idx = (size_t)row * UU + col;
                if (MODE == 0) {
                    float s0 = 1.f / (1.f + expf(-v0));
                    float s1 = 1.f / (1.f + expf(-v1));
                    if (jb == 0) {
                        float2 hh = *(const float2*)(hvec + idx);
                        __half2 o = __floats2half2_rn(s0 * hh.x, s1 * hh.y);
                        *(__half2*)(g_rh + idx) = o;
                    } else {
                        float2 o; o.x = s0; o.y = s1;
                        *(float2*)(g_u + idx) = o;
                    }
                } else {
                    float t0 = tanhf(v0), t1 = tanhf(v1);
                    float2 uu = *(const float2*)(g_u + idx);
                    float2 hh = *(const float2*)(hvec + idx);
                    float2 o;
                    o.x = uu.x * hh.x + (1.f - uu.x) * t0;
                    o.y = uu.y * hh.y + (1.f - uu.y) * t1;
                    *(float2*)(newh + idx) = o;
                    part[mt][h2] = fmaf(o.x, pw[col], part[mt][h2]);
                    part[mt][h2] = fmaf(o.y, pw[col + 1], part[mt][h2]);
                }
            }
        }
    }

    if (MODE == 1) {
        __syncthreads();               // SM reads done; safe to alias srow
        if (tid < 128) srow[tid] = 0.f;
        __syncthreads();
#pragma unroll
        for (int mt = 0; mt < 2; mt++)
#pragma unroll
            for (int h2 = 0; h2 < 2; h2++) {
                int lr = wm * 32 + mt * 16 + h2 * 8 + (lane >> 2);
                atomicAdd(&srow[lr], part[mt][h2]);
            }
        __syncthreads();
        if (tid < 128) out[mbase + tid] = srow[tid] + pb[0];
    }
}

// ---------------- launch ------------------------------------------------------
extern "C" void kernel_launch(void* const* d_in, const int* in_sizes, int n_in,
                              void* d_out, int out_size) {
    const float* inp = (const float*)d_in[0];
    const float* h   = (const float*)d_in[1];
    const float* S   = (const float*)d_in[2];
    const float* gw  = (const float*)d_in[3];
    const float* gb  = (const float*)d_in[4];
    const float* cw  = (const float*)d_in[5];
    const float* cb  = (const float*)d_in[6];
    const float* pw  = (const float*)d_in[7];
    const float* pb  = (const float*)d_in[8];
    float* out  = (float*)d_out;
    float* newh = out + MROWS;

    setup_all<<<SETUP_TOTAL, 256>>>(h, S, gw, cw);

    // gate path
    spmm_pass1<0><<<dim3(NN, BB / 4), 128>>>(inp);
    spmm_pass2<0><<<dim3(NN, BB / 4), 128>>>(inp);
    gemm_kernel<0><<<dim3(MROWS / 128, 2), 256>>>(gb, h, nullptr, nullptr, nullptr, nullptr);

    // cand path (projection fused)
    spmm_pass1<1><<<dim3(NN, BB / 4), 128>>>(inp);
    spmm_pass2<1><<<dim3(NN, BB / 4), 128>>>(inp);
    gemm_kernel<1><<<dim3(MROWS / 128, 1), 256>>>(cb, h, newh, pw, pb, out);
}

// round 15
// speedup vs baseline: 1.0696x; 1.0696x over previous
#include <cuda_runtime.h>
#include <cuda_fp16.h>
#include <math.h>
#include <stdint.h>

// Problem constants
#define BB 128
#define NN 1024
#define UU 128
#define NM 3
#define SBLK 132           // per-step block: 128 hvec + 1 inp + 3 pad
#define KPAD 416           // 3*132 = 396 -> 416 (26 x 16)
#define NCH (KPAD / 16)    // 26 k-chunks
#define MROWS 131072
#define MAX_NNZ 64
#define NSTAGE 4           // GEMM pipeline depth

// g_Xh row layout (stride KPAD, fp16):
//   [0..127] x0 hvec  [128] x0 inp [129..131] pad
//   [132..259] x1     [260] x1 inp [261..263] pad
//   [264..391] x2     [392] x2 inp [393..415] pad

// ---------------- scratch -----------------------------------------------------
__device__ __half g_h16[(size_t)MROWS * UU];    // fp16 copy of h input
__device__ __half g_Xh[(size_t)MROWS * KPAD];   // fp16 Xcat (A operand)
__device__ __half g_rh[(size_t)MROWS * UU];     // r*h (fp16)
__device__ float  g_u [(size_t)MROWS * UU];
__device__ __half g_Wgt[256 * KPAD];            // gate W^T [N][K] fp16
__device__ __half g_Wct[128 * KPAD];            // cand W^T [N][K] fp16
__device__ int    g_csr_cnt[NN];
__device__ int    g_csr_col[NN * MAX_NNZ];
__device__ float  g_csr_val[NN * MAX_NNZ];

// ---------------- helpers -----------------------------------------------------
__device__ __forceinline__ unsigned smem_u32(const void* p) {
    return (unsigned)__cvta_generic_to_shared(p);
}
__device__ __forceinline__ void cp16(unsigned dst, const void* src) {
    asm volatile("cp.async.cg.shared.global [%0], [%1], 16;" :: "r"(dst), "l"(src));
}
__device__ __forceinline__ void cp_commit() { asm volatile("cp.async.commit_group;"); }
__device__ __forceinline__ void cp_wait2()  { asm volatile("cp.async.wait_group 2;"); }

__device__ __forceinline__ void ldsm_x4(uint32_t* r, uint32_t a) {
    asm volatile("ldmatrix.sync.aligned.m8n8.x4.shared.b16 {%0,%1,%2,%3}, [%4];"
                 : "=r"(r[0]), "=r"(r[1]), "=r"(r[2]), "=r"(r[3]) : "r"(a));
}
__device__ __forceinline__ void mma_f16(float* c, const uint32_t* a, const uint32_t* b) {
    asm volatile("mma.sync.aligned.m16n8k16.row.col.f32.f16.f16.f32 "
                 "{%0,%1,%2,%3}, {%4,%5,%6,%7}, {%8,%9}, {%0,%1,%2,%3};"
                 : "+f"(c[0]), "+f"(c[1]), "+f"(c[2]), "+f"(c[3])
                 : "r"(a[0]), "r"(a[1]), "r"(a[2]), "r"(a[3]), "r"(b[0]), "r"(b[1]));
}

__device__ __forceinline__ void h_store4(__half* p, float4 v) {
    __half2 h01 = __floats2half2_rn(v.x, v.y);
    __half2 h23 = __floats2half2_rn(v.z, v.w);
    uint2 u; u.x = *(uint32_t*)&h01; u.y = *(uint32_t*)&h23;
    *(uint2*)p = u;
}
__device__ __forceinline__ void h_store1pad(__half* p, float v) {
    __half2 h = __floats2half2_rn(v, 0.f);
    uint2 u; u.x = *(uint32_t*)&h; u.y = 0u;
    *(uint2*)p = u;
}
__device__ __forceinline__ float4 h_load4(const __half* p) {
    uint2 u = *(const uint2*)p;
    __half2 p01 = *(__half2*)&u.x, p23 = *(__half2*)&u.y;
    float2 f01 = __half22float2(p01), f23 = __half22float2(p23);
    return make_float4(f01.x, f01.y, f23.x, f23.y);
}
__device__ __forceinline__ void fma4(float4& a, float s, float4 v) {
    a.x = fmaf(s, v.x, a.x); a.y = fmaf(s, v.y, a.y);
    a.z = fmaf(s, v.z, a.z); a.w = fmaf(s, v.w, a.w);
}

// 4-way unrolled fp16 sparse gather with 4 independent accumulators
__device__ __forceinline__ void gather_acc_h(
    const __half* __restrict__ base, size_t rowstride, int lane,
    const int* scol, const float* sval, int cnt,
    const float* sextra, float4& aout, float& a1out, bool lane0)
{
    float4 a0 = make_float4(0.f,0.f,0.f,0.f), a1v = a0, a2 = a0, a3 = a0;
    float e0 = 0.f, e1 = 0.f, e2 = 0.f, e3 = 0.f;
    int i = 0;
    for (; i + 4 <= cnt; i += 4) {
        int n0 = scol[i], n1 = scol[i+1], n2 = scol[i+2], n3 = scol[i+3];
        float s0 = sval[i], s1 = sval[i+1], s2 = sval[i+2], s3 = sval[i+3];
        float4 v0 = h_load4(base + (size_t)n0 * rowstride + lane * 4);
        float4 v1 = h_load4(base + (size_t)n1 * rowstride + lane * 4);
        float4 v2 = h_load4(base + (size_t)n2 * rowstride + lane * 4);
        float4 v3 = h_load4(base + (size_t)n3 * rowstride + lane * 4);
        fma4(a0, s0, v0);
        fma4(a1v, s1, v1);
        fma4(a2, s2, v2);
        fma4(a3, s3, v3);
        if (lane0) {
            e0 = fmaf(s0, sextra[i],   e0);
            e1 = fmaf(s1, sextra[i+1], e1);
            e2 = fmaf(s2, sextra[i+2], e2);
            e3 = fmaf(s3, sextra[i+3], e3);
        }
    }
    for (; i < cnt; i++) {
        float s = sval[i];
        float4 v = h_load4(base + (size_t)scol[i] * rowstride + lane * 4);
        fma4(a0, s, v);
        if (lane0) e0 = fmaf(s, sextra[i], e0);
    }
    a0.x += a1v.x; a0.y += a1v.y; a0.z += a1v.z; a0.w += a1v.w;
    a2.x += a3.x;  a2.y += a3.y;  a2.z += a3.z;  a2.w += a3.w;
    aout.x = a0.x + a2.x; aout.y = a0.y + a2.y;
    aout.z = a0.z + a2.z; aout.w = a0.w + a2.w;
    a1out = (e0 + e1) + (e2 + e3);
}

// ---------------- merged setup: h2half | csr_build | wtrans x2 ----------------
#define SETUP_H2H   16384
#define SETUP_CSR   (SETUP_H2H + 128)
#define SETUP_WG    (SETUP_CSR + KPAD)
#define SETUP_TOTAL (SETUP_WG + KPAD)

__global__ void __launch_bounds__(256) setup_all(
    const float* __restrict__ h, const float* __restrict__ S,
    const float* __restrict__ gw, const float* __restrict__ cw)
{
    int bx = blockIdx.x, tid = threadIdx.x;
    if (bx < SETUP_H2H) {
        size_t i = (size_t)bx * 256 + tid;
        float4 v = *(const float4*)(h + i * 4);
        h_store4(g_h16 + i * 4, v);
    } else if (bx < SETUP_CSR) {
        int w = ((bx - SETUP_H2H) * 256 + tid) >> 5;
        int lane = tid & 31;
        if (w >= NN) return;
        const float* row = S + (size_t)w * NN;
        int cnt = 0;
        for (int base = 0; base < NN; base += 32) {
            float v = row[base + lane];
            unsigned m = __ballot_sync(0xffffffffu, v != 0.f);
            if (v != 0.f) {
                int pos = cnt + __popc(m & ((1u << lane) - 1u));
                if (pos < MAX_NNZ) {
                    g_csr_col[w * MAX_NNZ + pos] = base + lane;
                    g_csr_val[w * MAX_NNZ + pos] = v;
                }
            }
            cnt += __popc(m);
        }
        if (lane == 0) g_csr_cnt[w] = cnt < MAX_NNZ ? cnt : MAX_NNZ;
    } else if (bx < SETUP_WG) {
        int k = bx - SETUP_CSR, j = tid;           // gate: 256 cols
        int s = k / SBLK, c = k - s * SBLK;
        float v = 0.f;
        if (s < NM && c < 129) {
            int corig = (c == 128) ? 0 : (c + 1);
            v = gw[(size_t)(corig * NM + s) * 256 + j];
        }
        g_Wgt[(size_t)j * KPAD + k] = __float2half_rn(v);
    } else {
        int k = bx - SETUP_WG, j = tid;            // cand: 128 cols
        if (j >= 128) return;
        int s = k / SBLK, c = k - s * SBLK;
        float v = 0.f;
        if (s < NM && c < 129) {
            int corig = (c == 128) ? 0 : (c + 1);
            v = cw[(size_t)(corig * NM + s) * 128 + j];
        }
        g_Wct[(size_t)j * KPAD + k] = __float2half_rn(v);
    }
}

// ---------------- diffusion pass 1: x0 copy + x1 (=S@x0), all fp16 ------------
template <int USE_RH>
__global__ void __launch_bounds__(128) spmm_pass1(const float* __restrict__ inp) {
    const __half* __restrict__ hvec = USE_RH ? (const __half*)g_rh : (const __half*)g_h16;
    int m = blockIdx.x;
    int g = threadIdx.x >> 5, lane = threadIdx.x & 31;
    int b = blockIdx.y * 4 + g;
    __shared__ int   scol[MAX_NNZ];
    __shared__ float sval[MAX_NNZ];
    __shared__ float sinp[4][MAX_NNZ];
    int cnt = g_csr_cnt[m];
    if (threadIdx.x < MAX_NNZ) {
        scol[threadIdx.x] = g_csr_col[m * MAX_NNZ + threadIdx.x];
        sval[threadIdx.x] = g_csr_val[m * MAX_NNZ + threadIdx.x];
    }
    __syncthreads();
    if (lane < cnt) sinp[g][lane] = inp[(size_t)b * NN + scol[lane]];
    if (cnt > 32 && lane + 32 < cnt) sinp[g][lane + 32] = inp[(size_t)b * NN + scol[lane + 32]];
    __syncwarp();

    size_t rowm = (size_t)b * NN + m;
    float4 a; float a1;
    gather_acc_h(hvec + (size_t)b * NN * UU, UU, lane, scol, sval, cnt,
                 sinp[g], a, a1, lane == 0);

    __half* Xh = g_Xh + rowm * KPAD;
    *(uint2*)(Xh + lane * 4) = *(const uint2*)(hvec + rowm * UU + lane * 4);
    h_store4(Xh + 132 + lane * 4, a);
    if (lane == 0) {
        h_store1pad(Xh + 128, inp[rowm]);   // x0 inp + pads 129..131
        h_store1pad(Xh + 260, a1);          // x1 inp + pads 261..263
    }
}

// ---------------- diffusion pass 2: x2 = 2*S@x1 - x0 (x1 from Xh cols 132+) ---
template <int USE_RH>
__global__ void __launch_bounds__(128) spmm_pass2(const float* __restrict__ inp) {
    const __half* __restrict__ hvec = USE_RH ? (const __half*)g_rh : (const __half*)g_h16;
    int m = blockIdx.x;
    int g = threadIdx.x >> 5, lane = threadIdx.x & 31;
    int b = blockIdx.y * 4 + g;
    __shared__ int   scol[MAX_NNZ];
    __shared__ float sval[MAX_NNZ];
    __shared__ float sx1i[4][MAX_NNZ];
    int cnt = g_csr_cnt[m];
    if (threadIdx.x < MAX_NNZ) {
        scol[threadIdx.x] = g_csr_col[m * MAX_NNZ + threadIdx.x];
        sval[threadIdx.x] = g_csr_val[m * MAX_NNZ + threadIdx.x];
    }
    __syncthreads();
    if (lane < cnt)
        sx1i[g][lane] = __half2float(g_Xh[((size_t)b * NN + scol[lane]) * KPAD + 260]);
    if (cnt > 32 && lane + 32 < cnt)
        sx1i[g][lane + 32] = __half2float(g_Xh[((size_t)b * NN + scol[lane + 32]) * KPAD + 260]);
    __syncwarp();

    size_t rowm = (size_t)b * NN + m;
    float4 a; float a1;
    gather_acc_h(g_Xh + (size_t)b * NN * KPAD + 132, KPAD, lane, scol, sval, cnt,
                 sx1i[g], a, a1, lane == 0);

    float4 x0 = h_load4(hvec + rowm * UU + lane * 4);
    float4 r;
    r.x = 2.f * a.x - x0.x;
    r.y = 2.f * a.y - x0.y;
    r.z = 2.f * a.z - x0.z;
    r.w = 2.f * a.w - x0.w;

    __half* Xh = g_Xh + rowm * KPAD;
    h_store4(Xh + 264 + lane * 4, r);                            // cols 264..391
    if (lane == 0) h_store1pad(Xh + 392, 2.f * a1 - inp[rowm]);  // 392..395
    if (lane < 5) {                                              // pads 396..415
        uint2 z; z.x = 0u; z.y = 0u;
        *(uint2*)(Xh + 396 + lane * 4) = z;
    }
}

// ---------------- fp16 tensor-core GEMM, 4-stage cp.async pipeline ------------
// BM=128 BN=128 BK=16, 256 thr (8 warps 4Mx2N), warp tile 32x64, m16n8k16.
// 4 smem stages (49152 B = static limit), wait_group 2 -> 3-chunk hide window.
// B fragments via ldsm_x4 (two j-tiles per load).
// MODE 0: gate (Wgt, N=256, grid.y=2): by0 -> g_rh(fp16) = sig*h ; by1 -> g_u = sig
// MODE 1: cand (Wct, N=128): newh = u*h+(1-u)*tanh ; fused proj -> out
template <int MODE>
__global__ void __launch_bounds__(256) gemm_kernel(
    const float* __restrict__ bias, const float* __restrict__ hvec,
    float* __restrict__ newh, const float* __restrict__ pw,
    const float* __restrict__ pb, float* __restrict__ out)
{
    __shared__ __align__(16) char smem_raw[NSTAGE * 2 * 128 * 24 * 2];   // 49152 B
    typedef __half (*SMv)[2][128 * 24];
    SMv SM = (SMv)smem_raw;
    float* srow = (float*)smem_raw;            // aliased; post-mainloop only

    const int tid = threadIdx.x;
    const int lane = tid & 31, wid = tid >> 5;
    const int wm = wid >> 1, wn = wid & 1;
    const size_t mbase = (size_t)blockIdx.x * 128;
    const int jb = (MODE == 0) ? blockIdx.y * 128 : 0;

    const __half* __restrict__ Wt = (MODE == 0) ? g_Wgt : g_Wct;

    const int lrow = tid >> 1, lhalf = tid & 1;
    const __half* srcA = g_Xh + (mbase + lrow) * KPAD + lhalf * 8;
    const __half* srcB = Wt + (size_t)(jb + lrow) * KPAD + lhalf * 8;
    const int dsti = lrow * 24 + lhalf * 8;

    float c[2][8][4];
#pragma unroll
    for (int mt = 0; mt < 2; mt++)
#pragma unroll
        for (int j = 0; j < 8; j++)
#pragma unroll
            for (int q = 0; q < 4; q++) c[mt][j][q] = 0.f;

    // preload stages 0..2 (one commit group each)
#pragma unroll
    for (int s = 0; s < NSTAGE - 1; s++) {
        int k0 = s * 16;
        cp16(smem_u32(&SM[s][0][dsti]), srcA + k0);
        cp16(smem_u32(&SM[s][1][dsti]), srcB + k0);
        cp_commit();
    }

    // A fragment addressing
    const int la = lane & 15;
    const int ka = (lane & 16) ? 8 : 0;
    const int arow = wm * 32 + la;
    // B fragment addressing for ldsm_x4 (two j-tiles): lane bit4 selects jj/jj+1
    const int nb = lane & 7;
    const int kb = (lane & 8) ? 8 : 0;
    const int joff = (lane & 16) ? 8 : 0;   // +8 B-rows for second j-tile

    for (int t = 0; t < NCH; t++) {
        int cur = t & (NSTAGE - 1);
        cp_wait2();
        __syncthreads();
        {
            int tp = t + NSTAGE - 1;
            if (tp < NCH) {
                int nb_ = tp & (NSTAGE - 1);
                int k0 = tp * 16;
                cp16(smem_u32(&SM[nb_][0][dsti]), srcA + k0);
                cp16(smem_u32(&SM[nb_][1][dsti]), srcB + k0);
            }
            cp_commit();   // commit every iteration (uniform group accounting)
        }

        uint32_t ah[2][4];
#pragma unroll
        for (int mt = 0; mt < 2; mt++)
            ldsm_x4(ah[mt], smem_u32(&SM[cur][0][(arow + mt * 16) * 24 + ka]));
#pragma unroll
        for (int jj = 0; jj < 8; jj += 2) {
            uint32_t bb[4];
            int bi = (wn * 64 + jj * 8 + joff + nb) * 24 + kb;
            ldsm_x4(bb, smem_u32(&SM[cur][1][bi]));
#pragma unroll
            for (int mt = 0; mt < 2; mt++) {
                mma_f16(c[mt][jj],     ah[mt], bb);
                mma_f16(c[mt][jj + 1], ah[mt], bb + 2);
            }
        }
    }

    // epilogue
    float part[2][2];
    if (MODE == 1) { part[0][0] = part[0][1] = part[1][0] = part[1][1] = 0.f; }

#pragma unroll
    for (int mt = 0; mt < 2; mt++) {
#pragma unroll
        for (int j = 0; j < 8; j++) {
            int row0 = (int)mbase + wm * 32 + mt * 16 + (lane >> 2);
            int col = wn * 64 + j * 8 + (lane & 3) * 2;
            int jg = jb + col;
            float b0 = bias[jg], b1 = bias[jg + 1];
#pragma unroll
            for (int h2 = 0; h2 < 2; h2++) {
                int row = row0 + h2 * 8;
                float v0 = c[mt][j][h2 * 2 + 0] + b0;
                float v1 = c[mt][j][h2 * 2 + 1] + b1;
                size_t idx = (size_t)row * UU + col;
                if (MODE == 0) {
                    float s0 = 1.f / (1.f + expf(-v0));
                    float s1 = 1.f / (1.f + expf(-v1));
                    if (jb == 0) {
                        float2 hh = *(const float2*)(hvec + idx);
                        __half2 o = __floats2half2_rn(s0 * hh.x, s1 * hh.y);
                        *(__half2*)(g_rh + idx) = o;
                    } else {
                        float2 o; o.x = s0; o.y = s1;
                        *(float2*)(g_u + idx) = o;
                    }
                } else {
                    float t0 = tanhf(v0), t1 = tanhf(v1);
                    float2 uu = *(const float2*)(g_u + idx);
                    float2 hh = *(const float2*)(hvec + idx);
                    float2 o;
                    o.x = uu.x * hh.x + (1.f - uu.x) * t0;
                    o.y = uu.y * hh.y + (1.f - uu.y) * t1;
                    *(float2*)(newh + idx) = o;
                    part[mt][h2] = fmaf(o.x, pw[col], part[mt][h2]);
                    part[mt][h2] = fmaf(o.y, pw[col + 1], part[mt][h2]);
                }
            }
        }
    }

    if (MODE == 1) {
        __syncthreads();               // SM reads done; safe to alias srow
        if (tid < 128) srow[tid] = 0.f;
        __syncthreads();
#pragma unroll
        for (int mt = 0; mt < 2; mt++)
#pragma unroll
            for (int h2 = 0; h2 < 2; h2++) {
                int lr = wm * 32 + mt * 16 + h2 * 8 + (lane >> 2);
                atomicAdd(&srow[lr], part[mt][h2]);
            }
        __syncthreads();
        if (tid < 128) out[mbase + tid] = srow[tid] + pb[0];
    }
}

// ---------------- launch ------------------------------------------------------
extern "C" void kernel_launch(void* const* d_in, const int* in_sizes, int n_in,
                              void* d_out, int out_size) {
    const float* inp = (const float*)d_in[0];
    const float* h   = (const float*)d_in[1];
    const float* S   = (const float*)d_in[2];
    const float* gw  = (const float*)d_in[3];
    const float* gb  = (const float*)d_in[4];
    const float* cw  = (const float*)d_in[5];
    const float* cb  = (const float*)d_in[6];
    const float* pw  = (const float*)d_in[7];
    const float* pb  = (const float*)d_in[8];
    float* out  = (float*)d_out;
    float* newh = out + MROWS;

    setup_all<<<SETUP_TOTAL, 256>>>(h, S, gw, cw);

    // gate path
    spmm_pass1<0><<<dim3(NN, BB / 4), 128>>>(inp);
    spmm_pass2<0><<<dim3(NN, BB / 4), 128>>>(inp);
    gemm_kernel<0><<<dim3(MROWS / 128, 2), 256>>>(gb, h, nullptr, nullptr, nullptr, nullptr);

    // cand path (projection fused)
    spmm_pass1<1><<<dim3(NN, BB / 4), 128>>>(inp);
    spmm_pass2<1><<<dim3(NN, BB / 4), 128>>>(inp);
    gemm_kernel<1><<<dim3(MROWS / 128, 1), 256>>>(cb, h, newh, pw, pb, out);
}